// round 4
// baseline (speedup 1.0000x reference)
#include <cuda_runtime.h>

// Problem constants
#define TPB    256
#define NSAMP  32000      // B*length = 32*1000
#define LEN    1000
#define TROW   1002
#define DDIM   16
#define EDIM   32
#define HDIM   64

typedef unsigned long long u64;

// Packed fp32x2 FMA (Blackwell sm_10x): d = a*b + c on two packed fp32 lanes.
__device__ __forceinline__ u64 ffma2(u64 a, u64 b, u64 c) {
    u64 d;
    asm("fma.rn.f32x2 %0, %1, %2, %3;" : "=l"(d) : "l"(a), "l"(b), "l"(c));
    return d;
}
__device__ __forceinline__ float hsum2(u64 v) {
    float lo, hi;
    asm("mov.b64 {%0, %1}, %2;" : "=f"(lo), "=f"(hi) : "l"(v));
    return lo + hi;
}
__device__ __forceinline__ u64 pack2(float lo, float hi) {
    u64 v;
    asm("mov.b64 %0, {%1, %2};" : "=l"(v) : "f"(lo), "f"(hi));
    return v;
}

// Scratch for per-(d, n) log|dJ| — deterministic reduction in a second kernel.
__device__ float g_dj[DDIM * NSAMP];

// Shared memory layout (bytes):
//   [0,       65536)  stageA : 32 u64 slots x TPB threads
//   [65536,  131072)  stageT : 32 u64 slots x TPB threads
//   [131072, 147456)  sW1    : 64x64 f32
//   [147456, 163840)  sW2    : 64x64 f32
//   [163840, 172032)  sW0e   : 64x32 f32 (embedding part of W0 rows)
//   [172032, 172288)  sW0x   : 64 f32 (last column of W0)
//   [172288, 172544)  sWo    : 64 f32
//   [172544, 173312)  sB0,sB1,sB2 : 3x64 f32
#define SMEM_BYTES 173312

// One hidden layer (64x64) applied to packed (a, t) simultaneously, in place.
__device__ __forceinline__ void layer64(const float* __restrict__ sW,
                                        const float* __restrict__ sB,
                                        u64* __restrict__ stageA,
                                        u64* __restrict__ stageT,
                                        u64* __restrict__ apk,
                                        u64* __restrict__ tpk,
                                        int tid)
{
#pragma unroll 1
    for (int i = 0; i < HDIM; i += 2) {
        u64 aa0 = 0, at0 = 0, aa1 = 0, at1 = 0;
        const ulonglong2* r0 = (const ulonglong2*)(sW + i * HDIM);
        const ulonglong2* r1 = r0 + 16;  // next row: 64 floats = 16 x 16B
#pragma unroll
        for (int k = 0; k < 16; ++k) {
            ulonglong2 w0 = r0[k];
            ulonglong2 w1 = r1[k];
            aa0 = ffma2(w0.x, apk[2 * k],     aa0);
            at0 = ffma2(w0.x, tpk[2 * k],     at0);
            aa1 = ffma2(w1.x, apk[2 * k],     aa1);
            at1 = ffma2(w1.x, tpk[2 * k],     at1);
            aa0 = ffma2(w0.y, apk[2 * k + 1], aa0);
            at0 = ffma2(w0.y, tpk[2 * k + 1], at0);
            aa1 = ffma2(w1.y, apk[2 * k + 1], aa1);
            at1 = ffma2(w1.y, tpk[2 * k + 1], at1);
        }
        float z0 = hsum2(aa0) + sB[i];
        float z1 = hsum2(aa1) + sB[i + 1];
        float g0 = (z0 >= 0.f) ? 1.f : 0.2f;
        float g1 = (z1 >= 0.f) ? 1.f : 0.2f;
        stageA[(i >> 1) * TPB + tid] = pack2(z0 * g0, z1 * g1);
        stageT[(i >> 1) * TPB + tid] = pack2(g0 * hsum2(at0), g1 * hsum2(at1));
    }
#pragma unroll
    for (int p = 0; p < 32; ++p) {
        apk[p] = stageA[p * TPB + tid];
        tpk[p] = stageT[p * TPB + tid];
    }
}

extern "C" __global__ void __launch_bounds__(TPB)
mlp_fwd_kernel(const float* __restrict__ x,  const float* __restrict__ emb,
               const float* __restrict__ W0, const float* __restrict__ b0,
               const float* __restrict__ W1, const float* __restrict__ b1,
               const float* __restrict__ W2, const float* __restrict__ b2,
               const float* __restrict__ Wo, const float* __restrict__ bo,
               float* __restrict__ out)
{
    extern __shared__ float smem[];
    const int tid = threadIdx.x;
    const int d   = blockIdx.y;

    u64*   stageA = (u64*)smem;
    u64*   stageT = stageA + 32 * TPB;
    float* sW1    = smem + 32768;        // 131072 B / 4
    float* sW2    = sW1 + 4096;
    float* sW0e   = sW2 + 4096;
    float* sW0x   = sW0e + 2048;
    float* sWo    = sW0x + 64;
    float* sB0    = sWo + 64;
    float* sB1    = sB0 + 64;
    float* sB2    = sB1 + 64;

    // ---- cooperative weight staging ----
    {
        const float4* g1 = (const float4*)(W1 + d * 4096);
        const float4* g2 = (const float4*)(W2 + d * 4096);
        float4* s1 = (float4*)sW1;
        float4* s2 = (float4*)sW2;
#pragma unroll
        for (int k = 0; k < 4; ++k) {
            s1[tid + k * TPB] = g1[tid + k * TPB];
            s2[tid + k * TPB] = g2[tid + k * TPB];
        }
        const float* g0 = W0 + d * HDIM * (EDIM + 1);
        for (int idx = tid; idx < HDIM * EDIM; idx += TPB) {
            int h = idx >> 5, e = idx & 31;
            sW0e[idx] = g0[h * 33 + e];
        }
        if (tid < HDIM) {
            sW0x[tid] = g0[tid * 33 + 32];
            sWo[tid]  = Wo[d * HDIM + tid];
            sB0[tid]  = b0[d * HDIM + tid];
            sB1[tid]  = b1[d * HDIM + tid];
            sB2[tid]  = b2[d * HDIM + tid];
        }
    }
    __syncthreads();

    const int n   = blockIdx.x * TPB + tid;     // grid.x*TPB == NSAMP exactly
    const int b   = n / LEN;
    const int l   = n - b * LEN;
    const int row = b * TROW + 2 + l;           // LAGS = 2
    const float xt = x[row * DDIM + d];

    // Pack the 32-wide embedding into 16 f32x2 regs.
    u64 epk[16];
    {
        const float4* er = (const float4*)(emb + (size_t)row * EDIM);
#pragma unroll
        for (int k = 0; k < 8; ++k) {
            float4 v = er[k];
            epk[2 * k]     = pack2(v.x, v.y);
            epk[2 * k + 1] = pack2(v.z, v.w);
        }
    }

    // ---- layer 0: z0 = W0e @ emb + W0x * x + b0 ; t0 = g0 * W0x ----
#pragma unroll 1
    for (int i = 0; i < HDIM; i += 2) {
        u64 a0 = 0, a1 = 0;
        const ulonglong2* r0 = (const ulonglong2*)(sW0e + i * EDIM);
        const ulonglong2* r1 = r0 + 8;  // next row: 32 floats = 8 x 16B
#pragma unroll
        for (int k = 0; k < 8; ++k) {
            ulonglong2 w0 = r0[k];
            ulonglong2 w1 = r1[k];
            a0 = ffma2(w0.x, epk[2 * k],     a0);
            a1 = ffma2(w1.x, epk[2 * k],     a1);
            a0 = ffma2(w0.y, epk[2 * k + 1], a0);
            a1 = ffma2(w1.y, epk[2 * k + 1], a1);
        }
        float wx0 = sW0x[i], wx1 = sW0x[i + 1];
        float z0 = hsum2(a0) + wx0 * xt + sB0[i];
        float z1 = hsum2(a1) + wx1 * xt + sB0[i + 1];
        float g0 = (z0 >= 0.f) ? 1.f : 0.2f;
        float g1 = (z1 >= 0.f) ? 1.f : 0.2f;
        stageA[(i >> 1) * TPB + tid] = pack2(z0 * g0, z1 * g1);
        stageT[(i >> 1) * TPB + tid] = pack2(g0 * wx0, g1 * wx1);
    }

    u64 apk[32], tpk[32];
#pragma unroll
    for (int p = 0; p < 32; ++p) {
        apk[p] = stageA[p * TPB + tid];
        tpk[p] = stageT[p * TPB + tid];
    }

    // ---- layers 1 and 2 ----
    layer64(sW1, sB1, stageA, stageT, apk, tpk, tid);
    layer64(sW2, sB2, stageA, stageT, apk, tpk, tid);

    // ---- output head: res = Wo@a2 + bo ; dJ = Wo@t2 ----
    u64 ra = 0, rt = 0;
    const ulonglong2* wo = (const ulonglong2*)sWo;
#pragma unroll
    for (int k = 0; k < 16; ++k) {
        ulonglong2 w = wo[k];
        ra = ffma2(w.x, apk[2 * k],     ra);
        rt = ffma2(w.x, tpk[2 * k],     rt);
        ra = ffma2(w.y, apk[2 * k + 1], ra);
        rt = ffma2(w.y, tpk[2 * k + 1], rt);
    }
    out[n * DDIM + d] = hsum2(ra) + bo[d];
    g_dj[d * NSAMP + n] = logf(fabsf(hsum2(rt)));
}

extern "C" __global__ void __launch_bounds__(256)
reduce_logdet_kernel(float* __restrict__ out)
{
    int n = blockIdx.x * 256 + threadIdx.x;
    if (n < NSAMP) {
        float s = 0.f;
#pragma unroll
        for (int d = 0; d < DDIM; ++d) s += g_dj[d * NSAMP + n];
        out[NSAMP * DDIM + n] = s;   // logdet region after residuals
    }
}

extern "C" void kernel_launch(void* const* d_in, const int* in_sizes, int n_in,
                              void* d_out, int out_size)
{
    const float* x   = (const float*)d_in[0];
    const float* emb = (const float*)d_in[1];
    const float* W0  = (const float*)d_in[2];
    const float* b0  = (const float*)d_in[3];
    const float* W1  = (const float*)d_in[4];
    const float* b1  = (const float*)d_in[5];
    const float* W2  = (const float*)d_in[6];
    const float* b2  = (const float*)d_in[7];
    const float* Wo  = (const float*)d_in[8];
    const float* bo  = (const float*)d_in[9];
    float* out = (float*)d_out;

    // Idempotent opt-in for >48KB dynamic smem (not a stream op; capture-safe).
    cudaFuncSetAttribute(mlp_fwd_kernel,
                         cudaFuncAttributeMaxDynamicSharedMemorySize, SMEM_BYTES);

    dim3 grid(NSAMP / TPB, DDIM);   // (125, 16)
    mlp_fwd_kernel<<<grid, TPB, SMEM_BYTES>>>(x, emb, W0, b0, W1, b1, W2, b2,
                                              Wo, bo, out);
    reduce_logdet_kernel<<<(NSAMP + 255) / 256, 256>>>(out);
}